// round 16
// baseline (speedup 1.0000x reference)
#include <cuda_runtime.h>
#include <cuda_fp16.h>
#include <math_constants.h>

#define NN 50000
#define EE 800000
#define HH 4
#define CC 64
#define DE 16
#define GG 64
#define HC 256   // H*C
#define NEG_SLOPE 0.2f
#define GN_EPS 1e-5f

// ---------------- device scratch (no allocations allowed) ----------------
__device__ __half g_xh[NN * HC];    // projected node features, fp16 [N, H*C] (25.6 MB)
__device__ float  g_asrc[NN * HH];  // per-node src attention logits (fp32)
__device__ float  g_adst[NN * HH];  // per-node dst attention logits (fp32)
__device__ float  g_denom[NN * HH]; // segment sum of exp per (dst, h)
__device__ float  g_vedge[DE * HH]; // folded W_edge @ att_edge, layout [d][h]

__device__ __forceinline__ void red_add_v4(float* p, float a, float b, float c, float d) {
    asm volatile("red.global.add.v4.f32 [%0], {%1, %2, %3, %4};"
                 :: "l"(p), "f"(a), "f"(b), "f"(c), "f"(d) : "memory");
}

// Convert 4 packed halves (loaded as float2 = 8B) to float4.
__device__ __forceinline__ float4 h4f(float2 raw) {
    __half2 lo = *(__half2*)&raw.x;
    __half2 hi = *(__half2*)&raw.y;
    float2 a = __half22float2(lo);
    float2 b = __half22float2(hi);
    return make_float4(a.x, a.y, b.x, b.y);
}

// ---------------- kernels ----------------

// Zero the y output region and softmax denominators.
__global__ void k_init(float* __restrict__ outy) {
    int i = blockIdx.x * blockDim.x + threadIdx.x;
    int stride = gridDim.x * blockDim.x;
    for (int j = i; j < NN * CC; j += stride) outy[j] = 0.0f;
    for (int j = i; j < NN * HH; j += stride) g_denom[j] = 0.0f;
}

// v[d][h] = sum_c W_edge[d, h*C + c] * att_edge[h, c]   (tiny: 16x4)
__global__ void k_vedge(const float* __restrict__ We, const float* __restrict__ ae) {
    int t = threadIdx.x;           // 64 threads
    int d = t >> 2, h = t & 3;
    float s = 0.0f;
    #pragma unroll 16
    for (int c = 0; c < CC; c++)
        s = fmaf(We[d * HC + h * CC + c], ae[h * CC + c], s);
    g_vedge[d * HH + h] = s;
}

// x = node @ W (stored fp16), fused with fp32 a_src/a_dst reduction.
#define PROJ_ROWS 32
__global__ void k_proj(const float* __restrict__ node, const float* __restrict__ W,
                       const float* __restrict__ att_src, const float* __restrict__ att_dst) {
    __shared__ float sn[PROJ_ROWS][CC];
    __shared__ float s_s[8][PROJ_ROWS];
    __shared__ float s_d[8][PROJ_ROWS];
    int block0 = blockIdx.x * PROJ_ROWS;
    int tid = threadIdx.x;  // 256
    for (int i = tid; i < PROJ_ROWS * CC; i += 256) {
        int r = i >> 6, c = i & 63;
        int n = block0 + r;
        sn[r][c] = (n < NN) ? node[n * CC + c] : 0.0f;
    }
    __syncthreads();
    float acc[PROJ_ROWS];
    #pragma unroll
    for (int r = 0; r < PROJ_ROWS; r++) acc[r] = 0.0f;
    #pragma unroll 4
    for (int k = 0; k < CC; k++) {
        float wk = W[k * HC + tid];
        #pragma unroll
        for (int r = 0; r < PROJ_ROWS; r++) acc[r] = fmaf(sn[r][k], wk, acc[r]);
    }
    float as = att_src[tid], ad = att_dst[tid];
    int warp = tid >> 5, lane = tid & 31;
    #pragma unroll
    for (int r = 0; r < PROJ_ROWS; r++) {
        int n = block0 + r;
        if (n < NN) g_xh[(size_t)n * HC + tid] = __float2half_rn(acc[r]);
        float ps = acc[r] * as;
        float pd = acc[r] * ad;
        #pragma unroll
        for (int o = 16; o > 0; o >>= 1) {
            ps += __shfl_xor_sync(0xffffffffu, ps, o);
            pd += __shfl_xor_sync(0xffffffffu, pd, o);
        }
        if (lane == 0) { s_s[warp][r] = ps; s_d[warp][r] = pd; }
    }
    __syncthreads();
    int r = tid & 31;
    int h = (tid >> 5) & 3;
    int which = tid >> 7;
    int n = block0 + r;
    if (n < NN) {
        if (which == 0) g_asrc[n * HH + h] = s_s[2 * h][r] + s_s[2 * h + 1][r];
        else            g_adst[n * HH + h] = s_d[2 * h][r] + s_d[2 * h + 1][r];
    }
}

// Edge pass, 2 edges per thread (EE even). All loads front-batched for MLP.
// ex = exp(lrelu(a_src[src]+a_dst[dst]+edge_attr@v)); no-max softmax is safe
// (logits O(10) << fp32 overflow; ratio mathematically identical).
__global__ void __launch_bounds__(256) k_edgeA(const int* __restrict__ ei,
                                               const float* __restrict__ edge_attr,
                                               float* __restrict__ att) {
    __shared__ float sv[DE * HH];
    if (threadIdx.x < DE * HH) sv[threadIdx.x] = g_vedge[threadIdx.x];
    __syncthreads();
    int i = blockIdx.x * blockDim.x + threadIdx.x;
    int e0 = i * 2;
    if (e0 >= EE) return;
    // 128 contiguous bytes per thread: both edges' attr rows. 8 independent LDG.128.
    const float4* ea = (const float4*)(edge_attr + (size_t)e0 * DE);
    float4 t0 = ea[0], t1 = ea[1], t2 = ea[2], t3 = ea[3];
    float4 u0 = ea[4], u1 = ea[5], u2 = ea[6], u3 = ea[7];
    int2 sp = *(const int2*)(ei + e0);        // src0, src1
    int2 dp = *(const int2*)(ei + EE + e0);   // dst0, dst1
    float4 s0 = *(const float4*)(g_asrc + sp.x * HH);
    float4 s1 = *(const float4*)(g_asrc + sp.y * HH);
    float4 d0 = *(const float4*)(g_adst + dp.x * HH);
    float4 d1 = *(const float4*)(g_adst + dp.y * HH);

    float ae0[HH] = {0.f, 0.f, 0.f, 0.f};
    float ae1[HH] = {0.f, 0.f, 0.f, 0.f};
    const float4 tq[4] = {t0, t1, t2, t3};
    const float4 uq[4] = {u0, u1, u2, u3};
    #pragma unroll
    for (int q = 0; q < 4; q++) {
        #pragma unroll
        for (int h = 0; h < HH; h++) {
            ae0[h] += tq[q].x * sv[(q * 4 + 0) * HH + h]
                    + tq[q].y * sv[(q * 4 + 1) * HH + h]
                    + tq[q].z * sv[(q * 4 + 2) * HH + h]
                    + tq[q].w * sv[(q * 4 + 3) * HH + h];
            ae1[h] += uq[q].x * sv[(q * 4 + 0) * HH + h]
                    + uq[q].y * sv[(q * 4 + 1) * HH + h]
                    + uq[q].z * sv[(q * 4 + 2) * HH + h]
                    + uq[q].w * sv[(q * 4 + 3) * HH + h];
        }
    }
    float a00 = s0.x + d0.x + ae0[0], a01 = s0.y + d0.y + ae0[1];
    float a02 = s0.z + d0.z + ae0[2], a03 = s0.w + d0.w + ae0[3];
    float a10 = s1.x + d1.x + ae1[0], a11 = s1.y + d1.y + ae1[1];
    float a12 = s1.z + d1.z + ae1[2], a13 = s1.w + d1.w + ae1[3];
    a00 = (a00 > 0.f) ? a00 : NEG_SLOPE * a00;  a01 = (a01 > 0.f) ? a01 : NEG_SLOPE * a01;
    a02 = (a02 > 0.f) ? a02 : NEG_SLOPE * a02;  a03 = (a03 > 0.f) ? a03 : NEG_SLOPE * a03;
    a10 = (a10 > 0.f) ? a10 : NEG_SLOPE * a10;  a11 = (a11 > 0.f) ? a11 : NEG_SLOPE * a11;
    a12 = (a12 > 0.f) ? a12 : NEG_SLOPE * a12;  a13 = (a13 > 0.f) ? a13 : NEG_SLOPE * a13;
    float e00 = __expf(a00), e01 = __expf(a01), e02 = __expf(a02), e03 = __expf(a03);
    float e10 = __expf(a10), e11 = __expf(a11), e12 = __expf(a12), e13 = __expf(a13);
    float4* ao = (float4*)(att + (size_t)e0 * HH);
    ao[0] = make_float4(e00, e01, e02, e03);
    ao[1] = make_float4(e10, e11, e12, e13);
    red_add_v4(&g_denom[dp.x * HH], e00, e01, e02, e03);
    red_add_v4(&g_denom[dp.y * HH], e10, e11, e12, e13);
}

// Pass C, 2 edges per 16-lane group. All 14 loads front-batched for MLP.
// att = ex/denom (written by lane 0), head-summed message RED into out[N,C].
__global__ void __launch_bounds__(256) k_edgeC(const int* __restrict__ ei,
                                               float* __restrict__ att,
                                               float* __restrict__ outy) {
    int t = blockIdx.x * blockDim.x + threadIdx.x;
    int pair = t >> 4;
    int lane = t & 15;
    int e0 = pair * 2;
    if (e0 >= EE) return;
    int2 sp = *(const int2*)(ei + e0);        // src0, src1
    int2 dp = *(const int2*)(ei + EE + e0);   // dst0, dst1
    float4 ex0 = *(const float4*)(att + (size_t)e0 * HH);
    float4 ex1 = *(const float4*)(att + (size_t)e0 * HH + HH);
    float4 dn0 = *(const float4*)(g_denom + dp.x * HH);
    float4 dn1 = *(const float4*)(g_denom + dp.y * HH);
    // Row = 256 halves = 64 8-byte chunks; head h occupies chunks [16h, 16h+16).
    const float2* xr0 = (const float2*)(g_xh + (size_t)sp.x * HC);
    const float2* xr1 = (const float2*)(g_xh + (size_t)sp.y * HC);
    float2 w00 = xr0[ 0 + lane], w01 = xr0[16 + lane];
    float2 w02 = xr0[32 + lane], w03 = xr0[48 + lane];
    float2 w10 = xr1[ 0 + lane], w11 = xr1[16 + lane];
    float2 w12 = xr1[32 + lane], w13 = xr1[48 + lane];

    float a00 = ex0.x / (dn0.x + 1e-16f), a01 = ex0.y / (dn0.y + 1e-16f);
    float a02 = ex0.z / (dn0.z + 1e-16f), a03 = ex0.w / (dn0.w + 1e-16f);
    float a10 = ex1.x / (dn1.x + 1e-16f), a11 = ex1.y / (dn1.y + 1e-16f);
    float a12 = ex1.z / (dn1.z + 1e-16f), a13 = ex1.w / (dn1.w + 1e-16f);
    if (lane == 0) {
        float4* ao = (float4*)(att + (size_t)e0 * HH);
        ao[0] = make_float4(a00, a01, a02, a03);
        ao[1] = make_float4(a10, a11, a12, a13);
    }
    float4 v0 = h4f(w00), v1 = h4f(w01), v2 = h4f(w02), v3 = h4f(w03);
    float r0 = fmaf(a00, v0.x, fmaf(a01, v1.x, fmaf(a02, v2.x, a03 * v3.x)));
    float r1 = fmaf(a00, v0.y, fmaf(a01, v1.y, fmaf(a02, v2.y, a03 * v3.y)));
    float r2 = fmaf(a00, v0.z, fmaf(a01, v1.z, fmaf(a02, v2.z, a03 * v3.z)));
    float r3 = fmaf(a00, v0.w, fmaf(a01, v1.w, fmaf(a02, v2.w, a03 * v3.w)));
    red_add_v4(outy + (size_t)dp.x * CC + lane * 4, r0, r1, r2, r3);
    v0 = h4f(w10); v1 = h4f(w11); v2 = h4f(w12); v3 = h4f(w13);
    r0 = fmaf(a10, v0.x, fmaf(a11, v1.x, fmaf(a12, v2.x, a13 * v3.x)));
    r1 = fmaf(a10, v0.y, fmaf(a11, v1.y, fmaf(a12, v2.y, a13 * v3.y)));
    r2 = fmaf(a10, v0.z, fmaf(a11, v1.z, fmaf(a12, v2.z, a13 * v3.z)));
    r3 = fmaf(a10, v0.w, fmaf(a11, v1.w, fmaf(a12, v2.w, a13 * v3.w)));
    red_add_v4(outy + (size_t)dp.y * CC + lane * 4, r0, r1, r2, r3);
}

// GraphNorm: one block (512 thr) per group; fused sum/sumsq stats pass.
__global__ void k_gn(const int* __restrict__ batch_ptr,
                     const float* __restrict__ bias,
                     const float* __restrict__ gnw,
                     const float* __restrict__ gnb,
                     const float* __restrict__ gnsc,
                     float* __restrict__ outy) {
    int g = blockIdx.x;
    __shared__ int s_lo, s_hi;
    if (threadIdx.x == 0) {
        int lo = 0, hi = NN;
        while (lo < hi) { int m = (lo + hi) >> 1; if (batch_ptr[m] < g) lo = m + 1; else hi = m; }
        s_lo = lo;
        int lo2 = lo, hi2 = NN;
        while (lo2 < hi2) { int m = (lo2 + hi2) >> 1; if (batch_ptr[m] < g + 1) lo2 = m + 1; else hi2 = m; }
        s_hi = lo2;
    }
    __syncthreads();
    int lo = s_lo, hi = s_hi;
    float cnt = (float)max(hi - lo, 1);
    int ch = threadIdx.x & 63;
    int ro = threadIdx.x >> 6;  // 0..7
    float b = bias[ch], w = gnw[ch], gb = gnb[ch], sc = gnsc[ch];
    __shared__ float redS[512], redQ[512];
    __shared__ float s_ms[64], s_rs[64];

    float s = 0.0f, q = 0.0f;
    for (int r = lo + ro; r < hi; r += 8) {
        float t = fmaf(outy[r * CC + ch], 0.25f, b);
        s += t;
        q = fmaf(t, t, q);
    }
    redS[threadIdx.x] = s;
    redQ[threadIdx.x] = q;
    __syncthreads();
    if (threadIdx.x < 64) {
        float S = 0.0f, Q = 0.0f;
        #pragma unroll
        for (int k = 0; k < 8; k++) {
            S += redS[threadIdx.x + 64 * k];
            Q += redQ[threadIdx.x + 64 * k];
        }
        float mean = S / cnt;
        float ms = mean * sc;
        float var = Q / cnt - 2.0f * ms * mean + ms * ms;
        s_ms[threadIdx.x] = ms;
        s_rs[threadIdx.x] = rsqrtf(var + GN_EPS);
    }
    __syncthreads();
    float ms = s_ms[ch];
    float rs = s_rs[ch];

    for (int r = lo + ro; r < hi; r += 8) {
        float t = (fmaf(outy[r * CC + ch], 0.25f, b) - ms) * rs;
        float y = fmaf(w, t, gb);
        outy[r * CC + ch] = fmaxf(y, 0.0f);
    }
}

// ---------------- launch ----------------
extern "C" void kernel_launch(void* const* d_in, const int* in_sizes, int n_in,
                              void* d_out, int out_size) {
    const float* node      = (const float*)d_in[0];
    const int*   ei        = (const int*)d_in[1];
    const float* edge_attr = (const float*)d_in[2];
    const int*   batch_ptr = (const int*)d_in[3];
    const float* W         = (const float*)d_in[4];
    const float* W_edge    = (const float*)d_in[5];
    const float* att_src   = (const float*)d_in[6];
    const float* att_dst   = (const float*)d_in[7];
    const float* att_edge  = (const float*)d_in[8];
    const float* bias      = (const float*)d_in[9];
    const float* gnw       = (const float*)d_in[10];
    const float* gnb       = (const float*)d_in[11];
    const float* gnsc      = (const float*)d_in[12];

    float* outy = (float*)d_out;                    // y region [N*C]
    float* att  = (float*)d_out + (size_t)NN * CC;  // att region [E*H]

    k_init<<<1024, 256>>>(outy);
    k_vedge<<<1, 64>>>(W_edge, att_edge);
    k_proj<<<(NN + PROJ_ROWS - 1) / PROJ_ROWS, 256>>>(node, W, att_src, att_dst);
    k_edgeA<<<(EE / 2 + 255) / 256, 256>>>(ei, edge_attr, att);
    k_edgeC<<<(EE / 2 * 16 + 255) / 256, 256>>>(ei, att, outy);
    k_gn<<<GG, 512>>>(batch_ptr, bias, gnw, gnb, gnsc, outy);
}